// round 8
// baseline (speedup 1.0000x reference)
#include <cuda_runtime.h>

// CapsuleLayer dynamic routing. C=10,B=128,N=1152,IN=8,OUT=16, 3 iters.
//   1) transpose W -> Wt4[c][j][n] (n innermost): coalesced phase-A loads.
//   2) fused priors + routing: one CTA per (c, batch-pair), 384 threads,
//      TWO CTAs resident per SM (24 warps) so one CTA's L2-bound priors
//      GEMM overlaps the other's LDS/shuffle-bound routing.
// Thread owns 3 route nodes: row0 in registers, rows1-2 in smem.
// Shift-free softmax + fused logit-update/accumulation sweeps (exact);
// iteration 0 exploits logits==0 -> uniform attention (S = N).

#define CCAP   10
#define BD     128
#define ND     1152
#define OUTD   16
#define THREADS 384
#define NWARPS  12
#define SROWS   768                        // smem rows per batch (rows 1-2)
#define NBLOCKS (CCAP * BD / 2)            // 640

// transposed weights scratch: 10*32*1152 float4 = 5.9 MB
__device__ float4 g_Wt[CCAP * 32 * ND];

__global__ void transpose_W_kernel(const float4* __restrict__ W4)
{
    int idx = blockIdx.x * blockDim.x + threadIdx.x;
    if (idx >= CCAP * 32 * ND) return;
    int n  = idx % ND;
    int t  = idx / ND;
    int j  = t % 32;
    int c  = t / 32;
    g_Wt[idx] = W4[((size_t)c * ND + n) * 32 + j];
}

// shared memory layout (floats)
#define PRI_SZ    (2 * 16 * SROWS)         // 24576 : pri_s[bb][o][row']
#define VRED_OFF  PRI_SZ
#define VRED_SZ   (NWARPS * 32)
#define SPRED_OFF (VRED_OFF + VRED_SZ)
#define OUTV_OFF  (SPRED_OFF + 2 * NWARPS)
#define SMEM_FLOATS (OUTV_OFF + 32)
#define SMEM_BYTES  (SMEM_FLOATS * 4)      // 100,064 B -> 2 CTAs fit 228KB

__global__ __launch_bounds__(THREADS, 2)
void caps_routing_kernel(const float* __restrict__ x,
                         float* __restrict__ out)
{
    extern __shared__ float sm[];
    float* pri_s = sm;                 // [2][16][SROWS]
    float* vred  = sm + VRED_OFF;      // [12][32]
    float* spred = sm + SPRED_OFF;     // [12][2]
    float* outv  = sm + OUTV_OFF;      // [2][16]

    const int tid  = threadIdx.x;
    const int lane = tid & 31;
    const int w    = tid >> 5;           // 0..11
    const int c    = blockIdx.x >> 6;
    const int b0   = (blockIdx.x & 63) * 2;

    const float4* __restrict__ X4 = (const float4*)x;

    // ------------- Phase A: priors, o-halved, smem rows first -------------
    float priA0[16], priA1[16];

    #pragma unroll
    for (int rr = 0; rr < 3; rr++) {
        const int rep = (rr + 1) % 3;    // 1, 2 (smem) then 0 (regs)
        const int n = tid + rep * THREADS;

        float xa[8], xb[8];
        {
            float4 u0 = X4[((size_t)b0 * ND + n) * 2 + 0];
            float4 u1 = X4[((size_t)b0 * ND + n) * 2 + 1];
            float4 u2 = X4[((size_t)(b0 + 1) * ND + n) * 2 + 0];
            float4 u3 = X4[((size_t)(b0 + 1) * ND + n) * 2 + 1];
            xa[0]=u0.x; xa[1]=u0.y; xa[2]=u0.z; xa[3]=u0.w;
            xa[4]=u1.x; xa[5]=u1.y; xa[6]=u1.z; xa[7]=u1.w;
            xb[0]=u2.x; xb[1]=u2.y; xb[2]=u2.z; xb[3]=u2.w;
            xb[4]=u3.x; xb[5]=u3.y; xb[6]=u3.z; xb[7]=u3.w;
        }

        #pragma unroll
        for (int h = 0; h < 2; h++) {
            float acc0[8], acc1[8];
            #pragma unroll
            for (int k = 0; k < 8; k++) { acc0[k] = 0.f; acc1[k] = 0.f; }

            const float4* wp = g_Wt + (size_t)c * 32 * ND + (size_t)(2 * h) * ND + n;
            #pragma unroll
            for (int i = 0; i < 8; i++) {
                const float va = xa[i], vb = xb[i];
                #pragma unroll
                for (int qq = 0; qq < 2; qq++) {
                    float4 wv = wp[(size_t)(i * 4 + qq) * ND];
                    acc0[qq*4+0] += va * wv.x; acc0[qq*4+1] += va * wv.y;
                    acc0[qq*4+2] += va * wv.z; acc0[qq*4+3] += va * wv.w;
                    acc1[qq*4+0] += vb * wv.x; acc1[qq*4+1] += vb * wv.y;
                    acc1[qq*4+2] += vb * wv.z; acc1[qq*4+3] += vb * wv.w;
                }
            }
            if (rep != 0) {
                const int j = (rep - 1) * THREADS + tid;
                #pragma unroll
                for (int k = 0; k < 8; k++) {
                    pri_s[(8 * h + k) * SROWS + j]        = acc0[k];  // bb=0
                    pri_s[(16 + 8 * h + k) * SROWS + j]   = acc1[k];  // bb=1
                }
            } else {
                #pragma unroll
                for (int k = 0; k < 8; k++) {
                    priA0[8 * h + k] = acc0[k];
                    priA1[8 * h + k] = acc1[k];
                }
            }
        }
    }
    __syncthreads();

    const float* __restrict__ p0 = pri_s + tid;              // + o*SROWS (+384)
    const float* __restrict__ p1 = pri_s + 16 * SROWS + tid;

    // logits [row] per batch
    float lg0[3] = {0.f, 0.f, 0.f};
    float lg1[3] = {0.f, 0.f, 0.f};

    // ---------------- Phase B: 3 fused routing sweeps ----------------
    #pragma unroll 1
    for (int it = 0; it < 3; it++) {
        float v0[16], v1[16];
        float sp0 = 0.f, sp1 = 0.f;

        if (it == 0) {
            // logits == 0: exactly uniform attention; S = ND.
            #pragma unroll
            for (int o = 0; o < 16; o++) {
                v0[o] = priA0[o] + p0[o * SROWS] + p0[o * SROWS + THREADS];
                v1[o] = priA1[o] + p1[o * SROWS] + p1[o * SROWS + THREADS];
            }
        } else {
            // batch 0 (sequential rows to bound register peak)
            {
                float d = 0.f;
                #pragma unroll
                for (int o = 0; o < 16; o++) d += outv[o] * priA0[o];
                lg0[0] += d;
                float e = __expf(lg0[0]);
                sp0 = e;
                #pragma unroll
                for (int o = 0; o < 16; o++) v0[o] = e * priA0[o];

                #pragma unroll
                for (int r = 1; r < 3; r++) {
                    float p[16];
                    d = 0.f;
                    #pragma unroll
                    for (int o = 0; o < 16; o++) {
                        p[o] = p0[o * SROWS + (r - 1) * THREADS];
                        d += outv[o] * p[o];
                    }
                    lg0[r] += d;
                    e = __expf(lg0[r]);
                    sp0 += e;
                    #pragma unroll
                    for (int o = 0; o < 16; o++) v0[o] += e * p[o];
                }
            }
            // batch 1
            {
                float d = 0.f;
                #pragma unroll
                for (int o = 0; o < 16; o++) d += outv[16 + o] * priA1[o];
                lg1[0] += d;
                float e = __expf(lg1[0]);
                sp1 = e;
                #pragma unroll
                for (int o = 0; o < 16; o++) v1[o] = e * priA1[o];

                #pragma unroll
                for (int r = 1; r < 3; r++) {
                    float p[16];
                    d = 0.f;
                    #pragma unroll
                    for (int o = 0; o < 16; o++) {
                        p[o] = p1[o * SROWS + (r - 1) * THREADS];
                        d += outv[16 + o] * p[o];
                    }
                    lg1[r] += d;
                    e = __expf(lg1[r]);
                    sp1 += e;
                    #pragma unroll
                    for (int o = 0; o < 16; o++) v1[o] += e * p[o];
                }
            }
        }

        // batch-merging component-splitting warp reduce (31 shfl):
        // bit-16 merges batches; bits 8/4/2/1 split components.
        float v[16];
        #pragma unroll
        for (int k = 0; k < 16; k++) {
            float s = (lane & 16) ? v0[k] : v1[k];
            float r = __shfl_xor_sync(0xffffffffu, s, 16);
            v[k] = ((lane & 16) ? v1[k] : v0[k]) + r;
        }
        #pragma unroll
        for (int k = 0; k < 8; k++) {
            float s = (lane & 8) ? v[k] : v[k + 8];
            float r = __shfl_xor_sync(0xffffffffu, s, 8);
            v[k] = ((lane & 8) ? v[k + 8] : v[k]) + r;
        }
        #pragma unroll
        for (int k = 0; k < 4; k++) {
            float s = (lane & 4) ? v[k] : v[k + 4];
            float r = __shfl_xor_sync(0xffffffffu, s, 4);
            v[k] = ((lane & 4) ? v[k + 4] : v[k]) + r;
        }
        #pragma unroll
        for (int k = 0; k < 2; k++) {
            float s = (lane & 2) ? v[k] : v[k + 2];
            float r = __shfl_xor_sync(0xffffffffu, s, 2);
            v[k] = ((lane & 2) ? v[k + 2] : v[k]) + r;
        }
        {
            float s = (lane & 1) ? v[0] : v[1];
            float r = __shfl_xor_sync(0xffffffffu, s, 1);
            v[0] = ((lane & 1) ? v[1] : v[0]) + r;
        }
        vred[w * 32 + lane] = v[0];

        if (it > 0) {   // sp: merge batches then butterfly
            float s = (lane & 16) ? sp0 : sp1;
            float r = __shfl_xor_sync(0xffffffffu, s, 16);
            float sp = ((lane & 16) ? sp1 : sp0) + r;
            #pragma unroll
            for (int d = 8; d; d >>= 1)
                sp += __shfl_xor_sync(0xffffffffu, sp, d);
            if ((lane & 15) == 0) spred[w * 2 + (lane >> 4)] = sp;
        }
        __syncthreads();

        // --- final 12-way reduce + squash (warp 0: lanes 0-15 bb0, 16-31 bb1) ---
        if (tid < 32) {
            const int fb = tid >> 4;
            float O = 0.f;
            #pragma unroll
            for (int j = 0; j < NWARPS; j++) O += vred[j * 32 + tid];
            float S;
            if (it == 0) {
                S = (float)ND;
            } else {
                S = 0.f;
                #pragma unroll
                for (int j = 0; j < NWARPS; j++) S += spred[j * 2 + fb];
            }
            float t = O / S;
            float sq = t * t;
            #pragma unroll
            for (int d = 8; d; d >>= 1)
                sq += __shfl_xor_sync(0xffffffffu, sq, d);
            float scale = sq / ((1.f + sq) * sqrtf(sq + 1e-8f));
            float val = t * scale;
            outv[tid] = val;
            if (it == 2)
                out[((size_t)(c * BD + b0 + fb)) * OUTD + (tid & 15)] = val;
        }
        __syncthreads();
    }
}

extern "C" void kernel_launch(void* const* d_in, const int* in_sizes, int n_in,
                              void* d_out, int out_size)
{
    const float* x = (const float*)d_in[0];
    const float* W = (const float*)d_in[1];
    // defensive: identify by size (x: 1,179,648 ; W: 1,474,560)
    if (n_in >= 2 && in_sizes[0] == CCAP * ND * 8 * OUTD) {
        x = (const float*)d_in[1];
        W = (const float*)d_in[0];
    }
    float* out = (float*)d_out;

    const int ttotal = CCAP * 32 * ND;
    transpose_W_kernel<<<(ttotal + 255) / 256, 256>>>((const float4*)W);

    cudaFuncSetAttribute(caps_routing_kernel,
                         cudaFuncAttributeMaxDynamicSharedMemorySize, SMEM_BYTES);
    caps_routing_kernel<<<NBLOCKS, THREADS, SMEM_BYTES>>>(x, out);
}

// round 9
// speedup vs baseline: 1.4964x; 1.4964x over previous
#include <cuda_runtime.h>

// CapsuleLayer dynamic routing. C=10,B=128,N=1152,IN=8,OUT=16, 3 iters.
// Prologue transposes BOTH operands to n-innermost layouts:
//     Wt4[c][j][n]  (j = 0..31 float4 groups)   - coalesced W loads
//     xT4[b][j][n]  (j = 0..1  float4 groups)   - coalesced x loads
// Main kernel: one CTA per (c, batch-pair), 576 threads; thread owns node
// tid (registers) + node tid+576 (smem, float4-packed). Shift-free softmax,
// fused logit-update/accumulation sweeps; iteration 0 uses logits==0 ->
// exactly uniform attention (S = N).

#define CCAP   10
#define BD     128
#define ND     1152
#define OUTD   16
#define HALF   576
#define THREADS 576
#define NWARPS  18
#define NBLOCKS (CCAP * BD / 2)   // 640

#define WT_ELEMS (CCAP * 32 * ND)   // 368,640 float4 (5.9 MB)
#define XT_ELEMS (BD * 2 * ND)      // 294,912 float4 (4.7 MB)

__device__ float4 g_Wt[WT_ELEMS];
__device__ float4 g_xT[XT_ELEMS];

__global__ void transpose_inputs_kernel(const float4* __restrict__ W4,
                                        const float4* __restrict__ X4)
{
    int idx = blockIdx.x * blockDim.x + threadIdx.x;
    if (idx < WT_ELEMS) {
        int n = idx % ND;
        int t = idx / ND;
        int j = t % 32;
        int c = t / 32;
        g_Wt[idx] = W4[((size_t)c * ND + n) * 32 + j];
    } else if (idx < WT_ELEMS + XT_ELEMS) {
        int k = idx - WT_ELEMS;
        int n = k % ND;
        int t = k / ND;
        int j = t % 2;
        int b = t / 2;
        g_xT[k] = X4[((size_t)b * ND + n) * 2 + j];
    }
}

// shared memory layout (floats)
#define PRI_SZ    (2 * 16 * HALF)          // 18432 : pri4[bb][g][n] float4-packed
#define VRED_OFF  PRI_SZ
#define VRED_SZ   (NWARPS * 32)
#define SPRED_OFF (VRED_OFF + VRED_SZ)
#define OUTV_OFF  (SPRED_OFF + 2 * NWARPS)
#define SMEM_FLOATS (OUTV_OFF + 32)
#define SMEM_BYTES  (SMEM_FLOATS * 4)      // ~76.3 KB

__global__ __launch_bounds__(THREADS, 1)
void caps_routing_kernel(float* __restrict__ out)
{
    extern __shared__ float sm[];
    float4* pri4  = (float4*)sm;        // [2][4][HALF] float4
    float*  vred  = sm + VRED_OFF;      // [18][32]
    float*  spred = sm + SPRED_OFF;     // [18][2]
    float*  outv  = sm + OUTV_OFF;      // [2][16]

    const int tid  = threadIdx.x;
    const int lane = tid & 31;
    const int w    = tid >> 5;           // 0..17
    const int c    = blockIdx.x >> 6;
    const int b0   = (blockIdx.x & 63) * 2;

    // ---------------- Phase A: priors ----------------
    float priA0[16], priA1[16];

    const float4* __restrict__ xr0 = g_xT + (size_t)(b0 * 2) * ND;        // b0, j=0/1
    const float4* __restrict__ xr1 = g_xT + (size_t)((b0 + 1) * 2) * ND;  // b0+1

    #pragma unroll
    for (int rep = 0; rep < 2; rep++) {
        const int n = tid + rep * HALF;

        float4 u0 = xr0[n];          // b0   i=0..3
        float4 u1 = xr0[ND + n];     // b0   i=4..7
        float4 u2 = xr1[n];          // b0+1 i=0..3
        float4 u3 = xr1[ND + n];     // b0+1 i=4..7
        float xa[8] = {u0.x, u0.y, u0.z, u0.w, u1.x, u1.y, u1.z, u1.w};
        float xb[8] = {u2.x, u2.y, u2.z, u2.w, u3.x, u3.y, u3.z, u3.w};

        float acc0[16], acc1[16];
        #pragma unroll
        for (int o = 0; o < 16; o++) { acc0[o] = 0.f; acc1[o] = 0.f; }

        const float4* wp = g_Wt + (size_t)c * 32 * ND + n;
        #pragma unroll
        for (int i = 0; i < 8; i++) {
            const float va = xa[i], vb = xb[i];
            #pragma unroll
            for (int q = 0; q < 4; q++) {
                float4 wv = wp[(size_t)(i * 4 + q) * ND];
                acc0[4*q+0] += va * wv.x; acc0[4*q+1] += va * wv.y;
                acc0[4*q+2] += va * wv.z; acc0[4*q+3] += va * wv.w;
                acc1[4*q+0] += vb * wv.x; acc1[4*q+1] += vb * wv.y;
                acc1[4*q+2] += vb * wv.z; acc1[4*q+3] += vb * wv.w;
            }
        }
        if (rep == 0) {
            #pragma unroll
            for (int o = 0; o < 16; o++) { priA0[o] = acc0[o]; priA1[o] = acc1[o]; }
        } else {
            #pragma unroll
            for (int g = 0; g < 4; g++) {
                pri4[g * HALF + tid] =
                    make_float4(acc0[4*g], acc0[4*g+1], acc0[4*g+2], acc0[4*g+3]);
                pri4[(4 + g) * HALF + tid] =
                    make_float4(acc1[4*g], acc1[4*g+1], acc1[4*g+2], acc1[4*g+3]);
            }
        }
    }
    __syncthreads();

    const float4* __restrict__ P0 = pri4 + tid;            // + g*HALF (bb=0)
    const float4* __restrict__ P1 = pri4 + 4 * HALF + tid; // + g*HALF (bb=1)

    // logits (shift-free): a = node rep0, b = node rep1; 0/1 = batch
    float la0 = 0.f, la1 = 0.f, lb0 = 0.f, lb1 = 0.f;

    // ---------------- Phase B: 3 fused routing sweeps ----------------
    #pragma unroll 1
    for (int it = 0; it < 3; it++) {
        float v0[16], v1[16];
        float sp0 = 0.f, sp1 = 0.f;

        if (it == 0) {
            // logits == 0: attention exactly uniform; S = ND.
            #pragma unroll
            for (int g = 0; g < 4; g++) {
                float4 q0 = P0[g * HALF];
                float4 q1 = P1[g * HALF];
                v0[4*g+0] = priA0[4*g+0] + q0.x; v0[4*g+1] = priA0[4*g+1] + q0.y;
                v0[4*g+2] = priA0[4*g+2] + q0.z; v0[4*g+3] = priA0[4*g+3] + q0.w;
                v1[4*g+0] = priA1[4*g+0] + q1.x; v1[4*g+1] = priA1[4*g+1] + q1.y;
                v1[4*g+2] = priA1[4*g+2] + q1.z; v1[4*g+3] = priA1[4*g+3] + q1.w;
            }
        } else {
            // fused: logit update -> exp -> weighted accumulation, one sweep.
            // batch 0
            {
                float d = 0.f;
                #pragma unroll
                for (int o = 0; o < 16; o++) d += outv[o] * priA0[o];
                la0 += d;
                float e = __expf(la0);
                sp0 = e;
                #pragma unroll
                for (int o = 0; o < 16; o++) v0[o] = e * priA0[o];

                float p[16];
                d = 0.f;
                #pragma unroll
                for (int g = 0; g < 4; g++) {
                    float4 q = P0[g * HALF];
                    p[4*g+0] = q.x; p[4*g+1] = q.y; p[4*g+2] = q.z; p[4*g+3] = q.w;
                    d += outv[4*g+0] * q.x + outv[4*g+1] * q.y
                       + outv[4*g+2] * q.z + outv[4*g+3] * q.w;
                }
                lb0 += d;
                e = __expf(lb0);
                sp0 += e;
                #pragma unroll
                for (int o = 0; o < 16; o++) v0[o] += e * p[o];
            }
            // batch 1
            {
                float d = 0.f;
                #pragma unroll
                for (int o = 0; o < 16; o++) d += outv[16 + o] * priA1[o];
                la1 += d;
                float e = __expf(la1);
                sp1 = e;
                #pragma unroll
                for (int o = 0; o < 16; o++) v1[o] = e * priA1[o];

                float p[16];
                d = 0.f;
                #pragma unroll
                for (int g = 0; g < 4; g++) {
                    float4 q = P1[g * HALF];
                    p[4*g+0] = q.x; p[4*g+1] = q.y; p[4*g+2] = q.z; p[4*g+3] = q.w;
                    d += outv[16+4*g+0] * q.x + outv[16+4*g+1] * q.y
                       + outv[16+4*g+2] * q.z + outv[16+4*g+3] * q.w;
                }
                lb1 += d;
                e = __expf(lb1);
                sp1 += e;
                #pragma unroll
                for (int o = 0; o < 16; o++) v1[o] += e * p[o];
            }
        }

        // batch-merging component-splitting warp reduce (31 shfl):
        // bit-16 merges batches; bits 8/4/2/1 split components.
        float v[16];
        #pragma unroll
        for (int k = 0; k < 16; k++) {
            float s = (lane & 16) ? v0[k] : v1[k];
            float r = __shfl_xor_sync(0xffffffffu, s, 16);
            v[k] = ((lane & 16) ? v1[k] : v0[k]) + r;
        }
        #pragma unroll
        for (int k = 0; k < 8; k++) {
            float s = (lane & 8) ? v[k] : v[k + 8];
            float r = __shfl_xor_sync(0xffffffffu, s, 8);
            v[k] = ((lane & 8) ? v[k + 8] : v[k]) + r;
        }
        #pragma unroll
        for (int k = 0; k < 4; k++) {
            float s = (lane & 4) ? v[k] : v[k + 4];
            float r = __shfl_xor_sync(0xffffffffu, s, 4);
            v[k] = ((lane & 4) ? v[k + 4] : v[k]) + r;
        }
        #pragma unroll
        for (int k = 0; k < 2; k++) {
            float s = (lane & 2) ? v[k] : v[k + 2];
            float r = __shfl_xor_sync(0xffffffffu, s, 2);
            v[k] = ((lane & 2) ? v[k + 2] : v[k]) + r;
        }
        {
            float s = (lane & 1) ? v[0] : v[1];
            float r = __shfl_xor_sync(0xffffffffu, s, 1);
            v[0] = ((lane & 1) ? v[1] : v[0]) + r;
        }
        vred[w * 32 + lane] = v[0];

        if (it > 0) {   // sp: merge batches then butterfly
            float s = (lane & 16) ? sp0 : sp1;
            float r = __shfl_xor_sync(0xffffffffu, s, 16);
            float sp = ((lane & 16) ? sp1 : sp0) + r;
            #pragma unroll
            for (int d = 8; d; d >>= 1)
                sp += __shfl_xor_sync(0xffffffffu, sp, d);
            if ((lane & 15) == 0) spred[w * 2 + (lane >> 4)] = sp;
        }
        __syncthreads();

        // --- final 18-way reduce + squash (warp 0: lanes 0-15 bb0, 16-31 bb1) ---
        if (tid < 32) {
            const int fb = tid >> 4;
            float O = 0.f;
            #pragma unroll
            for (int j = 0; j < NWARPS; j++) O += vred[j * 32 + tid];
            float S;
            if (it == 0) {
                S = (float)ND;
            } else {
                S = 0.f;
                #pragma unroll
                for (int j = 0; j < NWARPS; j++) S += spred[j * 2 + fb];
            }
            float t = O / S;
            float sq = t * t;
            #pragma unroll
            for (int d = 8; d; d >>= 1)
                sq += __shfl_xor_sync(0xffffffffu, sq, d);
            float scale = sq / ((1.f + sq) * sqrtf(sq + 1e-8f));
            float val = t * scale;
            outv[tid] = val;
            if (it == 2)
                out[((size_t)(c * BD + b0 + fb)) * OUTD + (tid & 15)] = val;
        }
        __syncthreads();
    }
}

extern "C" void kernel_launch(void* const* d_in, const int* in_sizes, int n_in,
                              void* d_out, int out_size)
{
    const float* x = (const float*)d_in[0];
    const float* W = (const float*)d_in[1];
    // defensive: identify by size (x: 1,179,648 ; W: 1,474,560)
    if (n_in >= 2 && in_sizes[0] == CCAP * ND * 8 * OUTD) {
        x = (const float*)d_in[1];
        W = (const float*)d_in[0];
    }
    float* out = (float*)d_out;

    const int ttotal = WT_ELEMS + XT_ELEMS;
    transpose_inputs_kernel<<<(ttotal + 255) / 256, 256>>>(
        (const float4*)W, (const float4*)x);

    cudaFuncSetAttribute(caps_routing_kernel,
                         cudaFuncAttributeMaxDynamicSharedMemorySize, SMEM_BYTES);
    caps_routing_kernel<<<NBLOCKS, THREADS, SMEM_BYTES>>>(out);
}